// round 2
// baseline (speedup 1.0000x reference)
#include <cuda_runtime.h>
#include <math.h>

#define D 4096
#define TWO_D 8192
#define THREADS 256
#define NWARPS (THREADS / 32)

__device__ double g_sum;
__device__ unsigned long long g_count;

__global__ void zero_acc_kernel() {
    g_sum = 0.0;
    g_count = 0ull;
}

__global__ __launch_bounds__(THREADS) void row_kernel(
    const float* __restrict__ outp,
    const float* __restrict__ gtp,
    const int* __restrict__ epochp)
{
    const int row = blockIdx.x;
    const size_t base = (size_t)row * TWO_D;
    const float4* __restrict__ out_r = (const float4*)(outp + base);
    const float4* __restrict__ out_i = (const float4*)(outp + base + D);
    const float4* __restrict__ gt_r  = (const float4*)(gtp + base);
    const float4* __restrict__ gt_i  = (const float4*)(gtp + base + D);

    float sum   = 0.0f;
    float maxsq = 0.0f;              // sq >= 0 always
    float gmax  = -INFINITY; int gidx = 0;
    float omax  = -INFINITY; int oidx = 0;

    #pragma unroll 4
    for (int j = threadIdx.x; j < D / 4; j += THREADS) {
        float4 or4 = out_r[j];
        float4 gr4 = gt_r[j];
        float4 oi4 = out_i[j];
        float4 gi4 = gt_i[j];

        float orv[4] = {or4.x, or4.y, or4.z, or4.w};
        float grv[4] = {gr4.x, gr4.y, gr4.z, gr4.w};
        float oiv[4] = {oi4.x, oi4.y, oi4.z, oi4.w};
        float giv[4] = {gi4.x, gi4.y, gi4.z, gi4.w};

        #pragma unroll
        for (int k = 0; k < 4; k++) {
            float er = grv[k] - orv[k];
            float ei = giv[k] - oiv[k];
            float sq = er * er + ei * ei;
            sum += sq;
            maxsq = fmaxf(maxsq, sq);
            int idx = j * 4 + k;
            if (grv[k] > gmax) { gmax = grv[k]; gidx = idx; }
            if (orv[k] > omax) { omax = orv[k]; oidx = idx; }
        }
    }

    // ---- warp reduction ----
    #pragma unroll
    for (int off = 16; off > 0; off >>= 1) {
        sum   += __shfl_down_sync(0xffffffff, sum, off);
        maxsq  = fmaxf(maxsq, __shfl_down_sync(0xffffffff, maxsq, off));
        float gv = __shfl_down_sync(0xffffffff, gmax, off);
        int   gi = __shfl_down_sync(0xffffffff, gidx, off);
        if (gv > gmax || (gv == gmax && gi < gidx)) { gmax = gv; gidx = gi; }
        float ov = __shfl_down_sync(0xffffffff, omax, off);
        int   oi = __shfl_down_sync(0xffffffff, oidx, off);
        if (ov > omax || (ov == omax && oi < oidx)) { omax = ov; oidx = oi; }
    }

    // ---- block reduction across warps ----
    __shared__ float s_sum[NWARPS];
    __shared__ float s_max[NWARPS];
    __shared__ float s_gv[NWARPS];  __shared__ int s_gi[NWARPS];
    __shared__ float s_ov[NWARPS];  __shared__ int s_oi[NWARPS];

    int lane = threadIdx.x & 31;
    int wid  = threadIdx.x >> 5;
    if (lane == 0) {
        s_sum[wid] = sum;  s_max[wid] = maxsq;
        s_gv[wid] = gmax;  s_gi[wid] = gidx;
        s_ov[wid] = omax;  s_oi[wid] = oidx;
    }
    __syncthreads();

    if (threadIdx.x == 0) {
        float tsum = s_sum[0], tmax = s_max[0];
        float tgv = s_gv[0]; int tgi = s_gi[0];
        float tov = s_ov[0]; int toi = s_oi[0];
        #pragma unroll
        for (int w = 1; w < NWARPS; w++) {
            tsum += s_sum[w];
            tmax = fmaxf(tmax, s_max[w]);
            if (s_gv[w] > tgv || (s_gv[w] == tgv && s_gi[w] < tgi)) { tgv = s_gv[w]; tgi = s_gi[w]; }
            if (s_ov[w] > tov || (s_ov[w] == tov && s_oi[w] < toi)) { tov = s_ov[w]; toi = s_oi[w]; }
        }

        int e = *epochp;
        // float32(0.5 * exp(-0.2)) computed in fp64 then cast, matching numpy
        float e_thresh = (e % 10 == 0) ? (float)(0.5 * exp(-0.2)) : 0.5f;
        float e_max = sqrtf(tmax);
        bool masked = (tgi == toi) && (e_max < e_thresh);

        if (!masked) atomicAdd(&g_sum, (double)tsum);
        atomicAdd(&g_count, masked ? 1ull : (unsigned long long)D);
    }
}

__global__ void finalize_kernel(float* __restrict__ outp) {
    outp[0] = (float)(g_sum / (1.0 + (double)g_count));
}

extern "C" void kernel_launch(void* const* d_in, const int* in_sizes, int n_in,
                              void* d_out, int out_size) {
    const float* outp   = (const float*)d_in[0];
    const float* gtp    = (const float*)d_in[1];
    const int*   epochp = (const int*)d_in[2];
    float* res = (float*)d_out;

    int rows = in_sizes[0] / TWO_D;   // 16384

    zero_acc_kernel<<<1, 1>>>();
    row_kernel<<<rows, THREADS>>>(outp, gtp, epochp);
    finalize_kernel<<<1, 1>>>(res);
}

// round 3
// speedup vs baseline: 1.0002x; 1.0002x over previous
#include <cuda_runtime.h>
#include <math.h>

#define D 4096
#define TWO_D 8192
#define THREADS 256
#define NWARPS (THREADS / 32)

__device__ double g_sum;
__device__ unsigned long long g_count;

__global__ void zero_acc_kernel() {
    g_sum = 0.0;
    g_count = 0ull;
}

__global__ __launch_bounds__(THREADS) void row_kernel(
    const float* __restrict__ outp,
    const float* __restrict__ gtp,
    const int* __restrict__ epochp)
{
    const int row = blockIdx.x;
    const size_t base = (size_t)row * TWO_D;
    const float4* __restrict__ out_r = (const float4*)(outp + base);
    const float4* __restrict__ out_i = (const float4*)(outp + base + D);
    const float4* __restrict__ gt_r  = (const float4*)(gtp + base);
    const float4* __restrict__ gt_i  = (const float4*)(gtp + base + D);

    float sum   = 0.0f;
    float maxsq = 0.0f;              // sq >= 0 always
    float gmax  = -INFINITY; int gidx = 0;
    float omax  = -INFINITY; int oidx = 0;

    #pragma unroll 4
    for (int j = threadIdx.x; j < D / 4; j += THREADS) {
        float4 or4 = out_r[j];
        float4 gr4 = gt_r[j];
        float4 oi4 = out_i[j];
        float4 gi4 = gt_i[j];

        float orv[4] = {or4.x, or4.y, or4.z, or4.w};
        float grv[4] = {gr4.x, gr4.y, gr4.z, gr4.w};
        float oiv[4] = {oi4.x, oi4.y, oi4.z, oi4.w};
        float giv[4] = {gi4.x, gi4.y, gi4.z, gi4.w};

        #pragma unroll
        for (int k = 0; k < 4; k++) {
            float er = grv[k] - orv[k];
            float ei = giv[k] - oiv[k];
            float sq = er * er + ei * ei;
            sum += sq;
            maxsq = fmaxf(maxsq, sq);
            int idx = j * 4 + k;
            if (grv[k] > gmax) { gmax = grv[k]; gidx = idx; }
            if (orv[k] > omax) { omax = orv[k]; oidx = idx; }
        }
    }

    // ---- warp reduction ----
    #pragma unroll
    for (int off = 16; off > 0; off >>= 1) {
        sum   += __shfl_down_sync(0xffffffff, sum, off);
        maxsq  = fmaxf(maxsq, __shfl_down_sync(0xffffffff, maxsq, off));
        float gv = __shfl_down_sync(0xffffffff, gmax, off);
        int   gi = __shfl_down_sync(0xffffffff, gidx, off);
        if (gv > gmax || (gv == gmax && gi < gidx)) { gmax = gv; gidx = gi; }
        float ov = __shfl_down_sync(0xffffffff, omax, off);
        int   oi = __shfl_down_sync(0xffffffff, oidx, off);
        if (ov > omax || (ov == omax && oi < oidx)) { omax = ov; oidx = oi; }
    }

    // ---- block reduction across warps ----
    __shared__ float s_sum[NWARPS];
    __shared__ float s_max[NWARPS];
    __shared__ float s_gv[NWARPS];  __shared__ int s_gi[NWARPS];
    __shared__ float s_ov[NWARPS];  __shared__ int s_oi[NWARPS];

    int lane = threadIdx.x & 31;
    int wid  = threadIdx.x >> 5;
    if (lane == 0) {
        s_sum[wid] = sum;  s_max[wid] = maxsq;
        s_gv[wid] = gmax;  s_gi[wid] = gidx;
        s_ov[wid] = omax;  s_oi[wid] = oidx;
    }
    __syncthreads();

    if (threadIdx.x == 0) {
        float tsum = s_sum[0], tmax = s_max[0];
        float tgv = s_gv[0]; int tgi = s_gi[0];
        float tov = s_ov[0]; int toi = s_oi[0];
        #pragma unroll
        for (int w = 1; w < NWARPS; w++) {
            tsum += s_sum[w];
            tmax = fmaxf(tmax, s_max[w]);
            if (s_gv[w] > tgv || (s_gv[w] == tgv && s_gi[w] < tgi)) { tgv = s_gv[w]; tgi = s_gi[w]; }
            if (s_ov[w] > tov || (s_ov[w] == tov && s_oi[w] < toi)) { tov = s_ov[w]; toi = s_oi[w]; }
        }

        int e = *epochp;
        // float32(0.5 * exp(-0.2)) computed in fp64 then cast, matching numpy
        float e_thresh = (e % 10 == 0) ? (float)(0.5 * exp(-0.2)) : 0.5f;
        float e_max = sqrtf(tmax);
        bool masked = (tgi == toi) && (e_max < e_thresh);

        if (!masked) atomicAdd(&g_sum, (double)tsum);
        atomicAdd(&g_count, masked ? 1ull : (unsigned long long)D);
    }
}

__global__ void finalize_kernel(float* __restrict__ outp) {
    outp[0] = (float)(g_sum / (1.0 + (double)g_count));
}

extern "C" void kernel_launch(void* const* d_in, const int* in_sizes, int n_in,
                              void* d_out, int out_size) {
    const float* outp   = (const float*)d_in[0];
    const float* gtp    = (const float*)d_in[1];
    const int*   epochp = (const int*)d_in[2];
    float* res = (float*)d_out;

    int rows = in_sizes[0] / TWO_D;   // 16384

    zero_acc_kernel<<<1, 1>>>();
    row_kernel<<<rows, THREADS>>>(outp, gtp, epochp);
    finalize_kernel<<<1, 1>>>(res);
}

// round 4
// speedup vs baseline: 1.0051x; 1.0049x over previous
#include <cuda_runtime.h>
#include <math.h>

#define D 4096
#define TWO_D 8192
#define THREADS 256
#define NWARPS (THREADS / 32)

__device__ double g_sum;
__device__ unsigned long long g_count;

__global__ void zero_acc_kernel() {
    g_sum = 0.0;
    g_count = 0ull;
}

__global__ __launch_bounds__(THREADS) void row_kernel(
    const float* __restrict__ outp,
    const float* __restrict__ gtp,
    const int* __restrict__ epochp)
{
    const int row = blockIdx.x;
    const size_t base = (size_t)row * TWO_D;
    const float4* __restrict__ out_r = (const float4*)(outp + base);
    const float4* __restrict__ out_i = (const float4*)(outp + base + D);
    const float4* __restrict__ gt_r  = (const float4*)(gtp + base);
    const float4* __restrict__ gt_i  = (const float4*)(gtp + base + D);

    float sum   = 0.0f;
    float maxsq = 0.0f;              // sq >= 0 always
    float gmax  = -INFINITY; int gidx = 0;
    float omax  = -INFINITY; int oidx = 0;

    #pragma unroll 4
    for (int j = threadIdx.x; j < D / 4; j += THREADS) {
        float4 or4 = out_r[j];
        float4 gr4 = gt_r[j];
        float4 oi4 = out_i[j];
        float4 gi4 = gt_i[j];

        float orv[4] = {or4.x, or4.y, or4.z, or4.w};
        float grv[4] = {gr4.x, gr4.y, gr4.z, gr4.w};
        float oiv[4] = {oi4.x, oi4.y, oi4.z, oi4.w};
        float giv[4] = {gi4.x, gi4.y, gi4.z, gi4.w};

        #pragma unroll
        for (int k = 0; k < 4; k++) {
            float er = grv[k] - orv[k];
            float ei = giv[k] - oiv[k];
            float sq = er * er + ei * ei;
            sum += sq;
            maxsq = fmaxf(maxsq, sq);
            int idx = j * 4 + k;
            if (grv[k] > gmax) { gmax = grv[k]; gidx = idx; }
            if (orv[k] > omax) { omax = orv[k]; oidx = idx; }
        }
    }

    // ---- warp reduction ----
    #pragma unroll
    for (int off = 16; off > 0; off >>= 1) {
        sum   += __shfl_down_sync(0xffffffff, sum, off);
        maxsq  = fmaxf(maxsq, __shfl_down_sync(0xffffffff, maxsq, off));
        float gv = __shfl_down_sync(0xffffffff, gmax, off);
        int   gi = __shfl_down_sync(0xffffffff, gidx, off);
        if (gv > gmax || (gv == gmax && gi < gidx)) { gmax = gv; gidx = gi; }
        float ov = __shfl_down_sync(0xffffffff, omax, off);
        int   oi = __shfl_down_sync(0xffffffff, oidx, off);
        if (ov > omax || (ov == omax && oi < oidx)) { omax = ov; oidx = oi; }
    }

    // ---- block reduction across warps ----
    __shared__ float s_sum[NWARPS];
    __shared__ float s_max[NWARPS];
    __shared__ float s_gv[NWARPS];  __shared__ int s_gi[NWARPS];
    __shared__ float s_ov[NWARPS];  __shared__ int s_oi[NWARPS];

    int lane = threadIdx.x & 31;
    int wid  = threadIdx.x >> 5;
    if (lane == 0) {
        s_sum[wid] = sum;  s_max[wid] = maxsq;
        s_gv[wid] = gmax;  s_gi[wid] = gidx;
        s_ov[wid] = omax;  s_oi[wid] = oidx;
    }
    __syncthreads();

    if (threadIdx.x == 0) {
        float tsum = s_sum[0], tmax = s_max[0];
        float tgv = s_gv[0]; int tgi = s_gi[0];
        float tov = s_ov[0]; int toi = s_oi[0];
        #pragma unroll
        for (int w = 1; w < NWARPS; w++) {
            tsum += s_sum[w];
            tmax = fmaxf(tmax, s_max[w]);
            if (s_gv[w] > tgv || (s_gv[w] == tgv && s_gi[w] < tgi)) { tgv = s_gv[w]; tgi = s_gi[w]; }
            if (s_ov[w] > tov || (s_ov[w] == tov && s_oi[w] < toi)) { tov = s_ov[w]; toi = s_oi[w]; }
        }

        int e = *epochp;
        // float32(0.5 * exp(-0.2)) computed in fp64 then cast, matching numpy
        float e_thresh = (e % 10 == 0) ? (float)(0.5 * exp(-0.2)) : 0.5f;
        float e_max = sqrtf(tmax);
        bool masked = (tgi == toi) && (e_max < e_thresh);

        if (!masked) atomicAdd(&g_sum, (double)tsum);
        atomicAdd(&g_count, masked ? 1ull : (unsigned long long)D);
    }
}

__global__ void finalize_kernel(float* __restrict__ outp) {
    outp[0] = (float)(g_sum / (1.0 + (double)g_count));
}

extern "C" void kernel_launch(void* const* d_in, const int* in_sizes, int n_in,
                              void* d_out, int out_size) {
    const float* outp   = (const float*)d_in[0];
    const float* gtp    = (const float*)d_in[1];
    const int*   epochp = (const int*)d_in[2];
    float* res = (float*)d_out;

    int rows = in_sizes[0] / TWO_D;   // 16384

    zero_acc_kernel<<<1, 1>>>();
    row_kernel<<<rows, THREADS>>>(outp, gtp, epochp);
    finalize_kernel<<<1, 1>>>(res);
}